// round 1
// baseline (speedup 1.0000x reference)
#include <cuda_runtime.h>

#define BB 2
#define SS 2048
#define DD 1024
#define HH 16
#define DK 64
#define MM (BB*SS)

// Scratch (device globals: allocation-free per harness rules)
__device__ float g_qh[(size_t)BB*HH*SS*DK];
__device__ float g_kh[(size_t)BB*HH*SS*DK];
__device__ float g_vh[(size_t)BB*HH*SS*DK];
__device__ float g_o [(size_t)BB*SS*DD];

// ---------------------------------------------------------------------------
// NT GEMM: C[M,N] = A[M,K] * W[N,K]^T + bias[N]
// MODE 0: row-major store (final projection)
// MODE 1: scatter to (B,H,S,Dk) layout (q/k/v projections)
// 64x64 tile, BK=16, 256 threads, 4x4 per thread.
// ---------------------------------------------------------------------------
template<int MODE>
__global__ __launch_bounds__(256)
void gemm_nt(const float* __restrict__ A,
             const float* __restrict__ W,
             const float* __restrict__ bias,
             float* __restrict__ C)
{
    const int K = DD, N = DD;
    __shared__ float As[16][65];
    __shared__ float Bs[16][65];
    const int bm = blockIdx.y * 64;
    const int bn = blockIdx.x * 64;
    const int t  = threadIdx.x;
    const int tx = t & 15, ty = t >> 4;
    const int lr = t >> 2;            // 0..63
    const int lc = (t & 3) << 2;      // 0,4,8,12

    float acc[4][4];
    #pragma unroll
    for (int i = 0; i < 4; i++)
        #pragma unroll
        for (int j = 0; j < 4; j++) acc[i][j] = 0.f;

    const float* Aptr = A + (size_t)(bm + lr) * K + lc;
    const float* Wptr = W + (size_t)(bn + lr) * K + lc;

    for (int k0 = 0; k0 < K; k0 += 16) {
        float4 a4 = *(const float4*)(Aptr + k0);
        float4 b4 = *(const float4*)(Wptr + k0);
        __syncthreads();
        As[lc+0][lr] = a4.x; As[lc+1][lr] = a4.y; As[lc+2][lr] = a4.z; As[lc+3][lr] = a4.w;
        Bs[lc+0][lr] = b4.x; Bs[lc+1][lr] = b4.y; Bs[lc+2][lr] = b4.z; Bs[lc+3][lr] = b4.w;
        __syncthreads();
        #pragma unroll
        for (int k = 0; k < 16; k++) {
            float av[4], bv[4];
            #pragma unroll
            for (int i = 0; i < 4; i++) av[i] = As[k][ty + 16*i];
            #pragma unroll
            for (int j = 0; j < 4; j++) bv[j] = Bs[k][tx + 16*j];
            #pragma unroll
            for (int i = 0; i < 4; i++)
                #pragma unroll
                for (int j = 0; j < 4; j++)
                    acc[i][j] += av[i] * bv[j];
        }
    }

    #pragma unroll
    for (int i = 0; i < 4; i++) {
        int m = bm + ty + 16*i;
        #pragma unroll
        for (int j = 0; j < 4; j++) {
            int n = bn + tx + 16*j;
            float val = acc[i][j] + bias[n];
            if (MODE == 0) {
                C[(size_t)m * N + n] = val;
            } else {
                int b  = m / SS, s  = m % SS;
                int h  = n / DK, dk = n % DK;
                C[(((size_t)b*HH + h)*SS + s)*DK + dk] = val;
            }
        }
    }
}

// ---------------------------------------------------------------------------
// Attention: one block = (b, h, 16 query rows). Full 16x2048 score row held in
// dynamic smem -> exact softmax in one K pass. 256 threads.
// smem: sc[16][2048] | Qs[16][64] | KV[64][66] (K transposed / V row-major)
// ---------------------------------------------------------------------------
#define KVP 66
#define ATTN_SMEM ((16*SS + 16*64 + 64*KVP) * (int)sizeof(float))

__global__ __launch_bounds__(256)
void attn_kernel(const float* __restrict__ qh,
                 const float* __restrict__ kh,
                 const float* __restrict__ vh,
                 const int*   __restrict__ mask,
                 float*       __restrict__ attn,
                 float*       __restrict__ o,
                 int write_attn)
{
    extern __shared__ float smem[];
    float* sc = smem;                 // [16][SS]
    float* Qs = smem + 16*SS;         // [16][64]
    float* KV = Qs + 16*64;           // [64][KVP]

    const int qt = blockIdx.x, h = blockIdx.y, b = blockIdx.z;
    const int t  = threadIdx.x;
    const int tx = t & 31;            // col base (cols tx, tx+32)
    const int ty = t >> 5;            // 0..7    (rows ty, ty+8)
    const int lk = t & 63;            // lane within a 64-wide row (loads)
    const int lrow0 = t >> 6;         // 0..3

    const float* qbase = qh + (((size_t)b*HH + h)*SS + (size_t)qt*16) * DK;
    const float* kbase = kh + ((size_t)b*HH + h)*SS*DK;
    const float* vbase = vh + ((size_t)b*HH + h)*SS*DK;

    // load Q tile (16x64)
    {
        float4 v4 = *(const float4*)(qbase + t*4);
        *(float4*)(Qs + t*4) = v4;
    }

    // ---- Phase 1: scores = Q K^T / 8 (+mask) ----
    for (int kt = 0; kt < SS/64; kt++) {
        __syncthreads();
        // load K tile transposed: KV[k][krow]
        #pragma unroll
        for (int rr = 0; rr < 16; rr++) {
            int krow = lrow0 + rr*4;
            KV[lk*KVP + krow] = kbase[(size_t)(kt*64 + krow)*DK + lk];
        }
        __syncthreads();

        float a00 = 0.f, a01 = 0.f, a10 = 0.f, a11 = 0.f;
        #pragma unroll 16
        for (int k = 0; k < 64; k++) {
            float kv0 = KV[k*KVP + tx];
            float kv1 = KV[k*KVP + tx + 32];
            float q0  = Qs[ty*64 + k];
            float q1  = Qs[(ty+8)*64 + k];
            a00 += q0*kv0; a01 += q0*kv1;
            a10 += q1*kv0; a11 += q1*kv1;
        }
        int c0 = kt*64 + tx, c1 = c0 + 32;
        int m0 = mask[(size_t)b*SS + c0];
        int m1 = mask[(size_t)b*SS + c1];
        const float scl = 0.125f;
        sc[ ty    *SS + c0] = m0 ? a00*scl : -1e9f;
        sc[ ty    *SS + c1] = m1 ? a01*scl : -1e9f;
        sc[(ty+8) *SS + c0] = m0 ? a10*scl : -1e9f;
        sc[(ty+8) *SS + c1] = m1 ? a11*scl : -1e9f;
    }
    __syncthreads();

    // ---- Phase 2: softmax per row (+ write attention probs) ----
    {
        int w = t >> 5, lane = t & 31;
        for (int r = w*2; r < w*2 + 2; r++) {
            float* row = sc + (size_t)r*SS;
            float mx = -1e30f;
            #pragma unroll 8
            for (int i = 0; i < SS/32; i++) mx = fmaxf(mx, row[lane + 32*i]);
            #pragma unroll
            for (int off = 16; off > 0; off >>= 1)
                mx = fmaxf(mx, __shfl_xor_sync(0xffffffffu, mx, off));
            float sum = 0.f;
            #pragma unroll 8
            for (int i = 0; i < SS/32; i++) {
                float e = __expf(row[lane + 32*i] - mx);
                row[lane + 32*i] = e;
                sum += e;
            }
            #pragma unroll
            for (int off = 16; off > 0; off >>= 1)
                sum += __shfl_xor_sync(0xffffffffu, sum, off);
            float inv = 1.f / sum;
            size_t abase = (((size_t)b*HH + h)*SS + (size_t)(qt*16 + r)) * SS;
            if (write_attn) {
                #pragma unroll 8
                for (int i = 0; i < SS/32; i++) {
                    float p = row[lane + 32*i] * inv;
                    row[lane + 32*i] = p;
                    attn[abase + lane + 32*i] = p;
                }
            } else {
                #pragma unroll 8
                for (int i = 0; i < SS/32; i++)
                    row[lane + 32*i] *= inv;
            }
        }
    }

    // ---- Phase 3: O = P @ V ----
    float o00 = 0.f, o01 = 0.f, o10 = 0.f, o11 = 0.f;
    for (int vt = 0; vt < SS/64; vt++) {
        __syncthreads();
        // load V tile row-major: KV[j][dk]
        #pragma unroll
        for (int rr = 0; rr < 16; rr++) {
            int j = lrow0 + rr*4;
            KV[j*KVP + lk] = vbase[(size_t)(vt*64 + j)*DK + lk];
        }
        __syncthreads();
        #pragma unroll 16
        for (int j = 0; j < 64; j++) {
            float v0 = KV[j*KVP + tx];
            float v1 = KV[j*KVP + tx + 32];
            float p0 = sc[ ty    *SS + vt*64 + j];
            float p1 = sc[(ty+8) *SS + vt*64 + j];
            o00 += p0*v0; o01 += p0*v1;
            o10 += p1*v0; o11 += p1*v1;
        }
    }
    {
        size_t r0 = (size_t)b*SS + qt*16 + ty;
        size_t r1 = r0 + 8;
        o[r0*DD + h*DK + tx     ] = o00;
        o[r0*DD + h*DK + tx + 32] = o01;
        o[r1*DD + h*DK + tx     ] = o10;
        o[r1*DD + h*DK + tx + 32] = o11;
    }
}

// ---------------------------------------------------------------------------
extern "C" void kernel_launch(void* const* d_in, const int* in_sizes, int n_in,
                              void* d_out, int out_size)
{
    const float* q    = (const float*)d_in[0];
    const float* k    = (const float*)d_in[1];
    const float* v    = (const float*)d_in[2];
    const int*   mask = (const int*)  d_in[3];
    const float* wq_w = (const float*)d_in[4];
    const float* wq_b = (const float*)d_in[5];
    const float* wk_w = (const float*)d_in[6];
    const float* wk_b = (const float*)d_in[7];
    const float* wv_w = (const float*)d_in[8];
    const float* wv_b = (const float*)d_in[9];
    const float* wo_w = (const float*)d_in[10];
    const float* wo_b = (const float*)d_in[11];

    float *qh_p, *kh_p, *vh_p, *o_p;
    cudaGetSymbolAddress((void**)&qh_p, g_qh);
    cudaGetSymbolAddress((void**)&kh_p, g_kh);
    cudaGetSymbolAddress((void**)&vh_p, g_vh);
    cudaGetSymbolAddress((void**)&o_p,  g_o);

    const long OUT_E  = (long)BB*SS*DD;              // 4,194,304
    const long ATTN_E = (long)BB*HH*SS*(long)SS;     // 134,217,728
    float* out_ptr  = nullptr;
    float* attn_ptr = nullptr;
    if ((long)out_size >= OUT_E + ATTN_E) {
        out_ptr  = (float*)d_out;
        attn_ptr = (float*)d_out + OUT_E;
    } else if ((long)out_size >= ATTN_E) {
        attn_ptr = (float*)d_out;
    } else {
        out_ptr  = (float*)d_out;
    }

    dim3 ggrid(DD/64, MM/64);   // 16 x 64
    gemm_nt<1><<<ggrid, 256>>>(q, wq_w, wq_b, qh_p);
    gemm_nt<1><<<ggrid, 256>>>(k, wk_w, wk_b, kh_p);
    gemm_nt<1><<<ggrid, 256>>>(v, wv_w, wv_b, vh_p);

    cudaFuncSetAttribute(attn_kernel,
                         cudaFuncAttributeMaxDynamicSharedMemorySize, ATTN_SMEM);
    attn_kernel<<<dim3(SS/16, HH, BB), 256, ATTN_SMEM>>>(
        qh_p, kh_p, vh_p, mask, attn_ptr, o_p, attn_ptr != nullptr ? 1 : 0);

    if (out_ptr)
        gemm_nt<0><<<ggrid, 256>>>(o_p, wo_w, wo_b, out_ptr);
}

// round 5
// speedup vs baseline: 1.6478x; 1.6478x over previous
#include <cuda_runtime.h>
#include <cstdint>

#define BB 2
#define SS 2048
#define DD 1024
#define HH 16
#define DK 64
#define MM (BB*SS)

// Scratch (device globals: allocation-free per harness rules)
__device__ float g_qh[(size_t)BB*HH*SS*DK];
__device__ float g_kh[(size_t)BB*HH*SS*DK];
__device__ float g_vh[(size_t)BB*HH*SS*DK];
__device__ float g_o [(size_t)BB*SS*DD];

// ---------------------------------------------------------------------------
// tf32 helpers: 3xTF32 split (hi = rna-rounded tf32, lo = tf32(x - hi))
// ---------------------------------------------------------------------------
__device__ __forceinline__ uint32_t f2tf(float x){
    uint32_t r; asm("cvt.rna.tf32.f32 %0, %1;" : "=r"(r) : "f"(x)); return r;
}
__device__ __forceinline__ void split_tf(float x, uint32_t& hi, uint32_t& lo){
    hi = f2tf(x);
    lo = f2tf(x - __uint_as_float(hi));
}
__device__ __forceinline__ void mma8(float* d, const uint32_t* a, const uint32_t* b){
    asm volatile("mma.sync.aligned.m16n8k8.row.col.f32.tf32.tf32.f32 "
        "{%0,%1,%2,%3},{%4,%5,%6,%7},{%8,%9},{%0,%1,%2,%3};"
        : "+f"(d[0]),"+f"(d[1]),"+f"(d[2]),"+f"(d[3])
        : "r"(a[0]),"r"(a[1]),"r"(a[2]),"r"(a[3]),"r"(b[0]),"r"(b[1]));
}

// ---------------------------------------------------------------------------
// Projection GEMM (tensor cores, 3xTF32): C[M,N] = A[M,K] * W[N,K]^T + bias
// Block tile 128x64, BK=32, 256 threads (8 warps as 4(M) x 2(N)), warp 32x32.
// MODE 0: row-major store.  MODE 1: scatter to (B,H,S,Dk).
// ---------------------------------------------------------------------------
#define PSTR 36
template<int MODE>
__global__ __launch_bounds__(256)
void proj_tf32(const float* __restrict__ A, const float* __restrict__ W,
               const float* __restrict__ bias, float* __restrict__ C)
{
    __shared__ float As[128][PSTR];
    __shared__ float Ws[64][PSTR];
    const int bm = blockIdx.y*128, bn = blockIdx.x*64;
    const int t = threadIdx.x, wid = t>>5, lane = t&31;
    const int qr = lane>>2, qc = lane&3;
    const int wm = (wid&3)*32, wn = (wid>>2)*32;

    float acc[2][4][4] = {};

    const int lr = t>>3;          // 0..31
    const int lc = (t&7)*4;       // 0,4,...,28

    for (int kc = 0; kc < DD; kc += 32) {
        __syncthreads();
        #pragma unroll
        for (int p = 0; p < 4; p++) {
            int row = lr + 32*p;
            float4 v4 = *(const float4*)(A + (size_t)(bm+row)*DD + kc + lc);
            *(float4*)&As[row][lc] = v4;
        }
        #pragma unroll
        for (int p = 0; p < 2; p++) {
            int row = lr + 32*p;
            float4 v4 = *(const float4*)(W + (size_t)(bn+row)*DD + kc + lc);
            *(float4*)&Ws[row][lc] = v4;
        }
        __syncthreads();
        #pragma unroll
        for (int ks = 0; ks < 4; ks++) {
            int k0 = ks*8;
            uint32_t ahi[2][4], alo[2][4], bhi[4][2], blo[4][2];
            #pragma unroll
            for (int mi = 0; mi < 2; mi++) {
                int r0 = wm + 16*mi + qr;
                split_tf(As[r0  ][k0+qc  ], ahi[mi][0], alo[mi][0]);
                split_tf(As[r0+8][k0+qc  ], ahi[mi][1], alo[mi][1]);
                split_tf(As[r0  ][k0+qc+4], ahi[mi][2], alo[mi][2]);
                split_tf(As[r0+8][k0+qc+4], ahi[mi][3], alo[mi][3]);
            }
            #pragma unroll
            for (int ni = 0; ni < 4; ni++) {
                int rn = wn + 8*ni + qr;
                split_tf(Ws[rn][k0+qc  ], bhi[ni][0], blo[ni][0]);
                split_tf(Ws[rn][k0+qc+4], bhi[ni][1], blo[ni][1]);
            }
            #pragma unroll
            for (int mi = 0; mi < 2; mi++)
                #pragma unroll
                for (int ni = 0; ni < 4; ni++) {
                    mma8(acc[mi][ni], ahi[mi], bhi[ni]);
                    mma8(acc[mi][ni], ahi[mi], blo[ni]);
                    mma8(acc[mi][ni], alo[mi], bhi[ni]);
                }
        }
    }
    #pragma unroll
    for (int mi = 0; mi < 2; mi++) {
        int r0 = bm + wm + 16*mi + qr;
        #pragma unroll
        for (int ni = 0; ni < 4; ni++) {
            int c0 = bn + wn + 8*ni + 2*qc;
            #pragma unroll
            for (int e = 0; e < 4; e++) {
                int m = r0 + ((e>=2) ? 8 : 0);
                int n = c0 + (e&1);
                float val = acc[mi][ni][e] + bias[n];
                if (MODE == 0) {
                    C[(size_t)m*DD + n] = val;
                } else {
                    int b = m/SS, s = m%SS, h = n/DK, dk = n%DK;
                    C[(((size_t)b*HH+h)*SS+s)*DK+dk] = val;
                }
            }
        }
    }
}

// ---------------------------------------------------------------------------
// Attention (tensor cores, 3xTF32). Block = (b, h, 16 q rows), 256 threads.
// Full 16x2048 score row in smem -> exact softmax.
// Phase1: warp w computes score cols [w*16, w*16+16) of each 128-col K chunk.
// Phase3: warp w computes output dk cols [8w, 8w+8).
// ---------------------------------------------------------------------------
#define SCP  2052
#define QSP  68
#define KVP2 68
#define ATTN_SMEM ((16*SCP + 16*QSP + 128*KVP2) * (int)sizeof(float))

__global__ __launch_bounds__(256)
void attn_tc(const float* __restrict__ qh, const float* __restrict__ kh,
             const float* __restrict__ vh, const int* __restrict__ mask,
             float* __restrict__ attn, float* __restrict__ o, int write_attn)
{
    extern __shared__ float smem[];
    float* sc  = smem;                 // [16][SCP]
    float* Qs  = smem + 16*SCP;        // [16][QSP]
    float* KVs = Qs  + 16*QSP;         // [128][KVP2]

    const int qt = blockIdx.x, h = blockIdx.y, b = blockIdx.z;
    const int t = threadIdx.x, w = t>>5, lane = t&31;
    const int qr = lane>>2, qc = lane&3;

    const float* qbase = qh + (((size_t)b*HH+h)*SS + (size_t)qt*16)*DK;
    const float* kbase = kh + ((size_t)b*HH+h)*SS*DK;
    const float* vbase = vh + ((size_t)b*HH+h)*SS*DK;

    // load Q tile (16x64)
    {
        int row = t>>4, col = (t&15)*4;
        float4 v4 = *(const float4*)(qbase + (size_t)row*DK + col);
        *(float4*)&Qs[row*QSP + col] = v4;
    }
    __syncthreads();

    // Q fragments (8 k-steps), hoisted for whole phase 1
    uint32_t qhi_f[8][4], qlo_f[8][4];
    #pragma unroll
    for (int ks = 0; ks < 8; ks++) {
        int k0 = ks*8;
        split_tf(Qs[ qr   *QSP + k0+qc  ], qhi_f[ks][0], qlo_f[ks][0]);
        split_tf(Qs[(qr+8)*QSP + k0+qc  ], qhi_f[ks][1], qlo_f[ks][1]);
        split_tf(Qs[ qr   *QSP + k0+qc+4], qhi_f[ks][2], qlo_f[ks][2]);
        split_tf(Qs[(qr+8)*QSP + k0+qc+4], qhi_f[ks][3], qlo_f[ks][3]);
    }

    // ---- Phase 1: scores ----
    for (int kb = 0; kb < SS/128; kb++) {
        __syncthreads();
        {
            int j = t>>4, col = (t&15)*4;
            #pragma unroll
            for (int p = 0; p < 8; p++) {
                float4 v4 = *(const float4*)(kbase + (size_t)(kb*128 + j + 16*p)*DK + col);
                *(float4*)&KVs[(j+16*p)*KVP2 + col] = v4;
            }
        }
        __syncthreads();
        float acc[2][4] = {};
        #pragma unroll
        for (int ks = 0; ks < 8; ks++) {
            int k0 = ks*8;
            uint32_t bhi[2][2], blo[2][2];
            #pragma unroll
            for (int ni = 0; ni < 2; ni++) {
                int rn = w*16 + 8*ni + qr;
                split_tf(KVs[rn*KVP2 + k0+qc  ], bhi[ni][0], blo[ni][0]);
                split_tf(KVs[rn*KVP2 + k0+qc+4], bhi[ni][1], blo[ni][1]);
            }
            #pragma unroll
            for (int ni = 0; ni < 2; ni++) {
                mma8(acc[ni], qhi_f[ks], bhi[ni]);
                mma8(acc[ni], qhi_f[ks], blo[ni]);
                mma8(acc[ni], qlo_f[ks], bhi[ni]);
            }
        }
        #pragma unroll
        for (int ni = 0; ni < 2; ni++) {
            int gc = kb*128 + w*16 + 8*ni + 2*qc;
            int m0 = mask[(size_t)b*SS + gc];
            int m1 = mask[(size_t)b*SS + gc + 1];
            sc[ qr   *SCP + gc  ] = m0 ? acc[ni][0]*0.125f : -1e9f;
            sc[ qr   *SCP + gc+1] = m1 ? acc[ni][1]*0.125f : -1e9f;
            sc[(qr+8)*SCP + gc  ] = m0 ? acc[ni][2]*0.125f : -1e9f;
            sc[(qr+8)*SCP + gc+1] = m1 ? acc[ni][3]*0.125f : -1e9f;
        }
    }
    __syncthreads();

    // ---- Phase 2: exact softmax per row (+ write attention probs) ----
    for (int r = w*2; r < w*2 + 2; r++) {
        float* row = sc + (size_t)r*SCP;
        float mx = -1e30f;
        #pragma unroll 8
        for (int i = 0; i < SS/32; i++) mx = fmaxf(mx, row[lane + 32*i]);
        #pragma unroll
        for (int off = 16; off > 0; off >>= 1)
            mx = fmaxf(mx, __shfl_xor_sync(0xffffffffu, mx, off));
        float sum = 0.f;
        #pragma unroll 8
        for (int i = 0; i < SS/32; i++) {
            float e = __expf(row[lane + 32*i] - mx);
            row[lane + 32*i] = e;
            sum += e;
        }
        #pragma unroll
        for (int off = 16; off > 0; off >>= 1)
            sum += __shfl_xor_sync(0xffffffffu, sum, off);
        float inv = 1.f / sum;
        size_t abase = (((size_t)b*HH + h)*SS + (size_t)(qt*16 + r)) * SS;
        if (write_attn) {
            #pragma unroll 8
            for (int i = 0; i < SS/32; i++) {
                float p = row[lane + 32*i] * inv;
                row[lane + 32*i] = p;
                attn[abase + lane + 32*i] = p;
            }
        } else {
            #pragma unroll 8
            for (int i = 0; i < SS/32; i++)
                row[lane + 32*i] *= inv;
        }
    }

    // ---- Phase 3: O = P @ V ----
    float oacc[4] = {};
    for (int vb = 0; vb < SS/128; vb++) {
        __syncthreads();
        {
            int j = t>>4, col = (t&15)*4;
            #pragma unroll
            for (int p = 0; p < 8; p++) {
                float4 v4 = *(const float4*)(vbase + (size_t)(vb*128 + j + 16*p)*DK + col);
                *(float4*)&KVs[(j+16*p)*KVP2 + col] = v4;
            }
        }
        __syncthreads();
        #pragma unroll
        for (int ks = 0; ks < 16; ks++) {
            int gj = vb*128 + ks*8;     // global contraction index (sc columns)
            uint32_t phi[4], plo[4], vhi[2], vlo[2];
            split_tf(sc[ qr   *SCP + gj+qc  ], phi[0], plo[0]);
            split_tf(sc[(qr+8)*SCP + gj+qc  ], phi[1], plo[1]);
            split_tf(sc[ qr   *SCP + gj+qc+4], phi[2], plo[2]);
            split_tf(sc[(qr+8)*SCP + gj+qc+4], phi[3], plo[3]);
            split_tf(KVs[(ks*8+qc  )*KVP2 + 8*w + qr], vhi[0], vlo[0]);
            split_tf(KVs[(ks*8+qc+4)*KVP2 + 8*w + qr], vhi[1], vlo[1]);
            mma8(oacc, phi, vhi);
            mma8(oacc, phi, vlo);
            mma8(oacc, plo, vhi);
        }
    }
    {
        size_t r0 = (size_t)b*SS + qt*16 + qr;
        int c0 = h*DK + 8*w + 2*qc;
        o[ r0   *DD + c0  ] = oacc[0];
        o[ r0   *DD + c0+1] = oacc[1];
        o[(r0+8)*DD + c0  ] = oacc[2];
        o[(r0+8)*DD + c0+1] = oacc[3];
    }
}

// ---------------------------------------------------------------------------
extern "C" void kernel_launch(void* const* d_in, const int* in_sizes, int n_in,
                              void* d_out, int out_size)
{
    const float* q    = (const float*)d_in[0];
    const float* k    = (const float*)d_in[1];
    const float* v    = (const float*)d_in[2];
    const int*   mask = (const int*)  d_in[3];
    const float* wq_w = (const float*)d_in[4];
    const float* wq_b = (const float*)d_in[5];
    const float* wk_w = (const float*)d_in[6];
    const float* wk_b = (const float*)d_in[7];
    const float* wv_w = (const float*)d_in[8];
    const float* wv_b = (const float*)d_in[9];
    const float* wo_w = (const float*)d_in[10];
    const float* wo_b = (const float*)d_in[11];

    float *qh_p, *kh_p, *vh_p, *o_p;
    cudaGetSymbolAddress((void**)&qh_p, g_qh);
    cudaGetSymbolAddress((void**)&kh_p, g_kh);
    cudaGetSymbolAddress((void**)&vh_p, g_vh);
    cudaGetSymbolAddress((void**)&o_p,  g_o);

    const long OUT_E  = (long)BB*SS*DD;              // 4,194,304
    const long ATTN_E = (long)BB*HH*SS*(long)SS;     // 134,217,728
    float* out_ptr  = nullptr;
    float* attn_ptr = nullptr;
    if ((long)out_size >= OUT_E + ATTN_E) {
        out_ptr  = (float*)d_out;
        attn_ptr = (float*)d_out + OUT_E;
    } else if ((long)out_size >= ATTN_E) {
        attn_ptr = (float*)d_out;
    } else {
        out_ptr  = (float*)d_out;
    }

    dim3 pgrid(DD/64, MM/128);   // 16 x 32
    proj_tf32<1><<<pgrid, 256>>>(q, wq_w, wq_b, qh_p);
    proj_tf32<1><<<pgrid, 256>>>(k, wk_w, wk_b, kh_p);
    proj_tf32<1><<<pgrid, 256>>>(v, wv_w, wv_b, vh_p);

    cudaFuncSetAttribute(attn_tc,
                         cudaFuncAttributeMaxDynamicSharedMemorySize, ATTN_SMEM);
    attn_tc<<<dim3(SS/16, HH, BB), 256, ATTN_SMEM>>>(
        qh_p, kh_p, vh_p, mask, attn_ptr, o_p, attn_ptr != nullptr ? 1 : 0);

    if (out_ptr)
        proj_tf32<0><<<pgrid, 256>>>(o_p, wo_w, wo_b, out_ptr);
}